// round 15
// baseline (speedup 1.0000x reference)
#include <cuda_runtime.h>
#include <cuda_fp16.h>
#include <math.h>
#include <stdint.h>

#define Bsz    8192
#define Ddim   256
#define MARGIN 0.3f
#define NGRID  1056               // sum_{jt<32} (2*jt+2)

// ---- dynamic SMEM: 4 bufs x (A 16KB + B 32KB) + njr(1KB) + njc(2KB) ----
#define SM_BUF(b)   ((b) * 49152)
#define SM_A        0
#define SM_B        16384
#define SM_NJR      196608
#define SM_NJC      197632
#define SMEM_TOTAL  199680

__device__ float        g_norms[Bsz];
__device__ float2       g_njl[Bsz];
__device__ __half       g_h[Bsz * Ddim];
__device__ uint2        g_v[Bsz];       // {enc(max pos v), enc(min neg v)}
__device__ unsigned int g_cnt;

__device__ __forceinline__ unsigned int enc(float f) {
    unsigned int u = __float_as_uint(f);
    return (u & 0x80000000u) ? ~u : (u | 0x80000000u);
}
__device__ __forceinline__ float dec(unsigned int u) {
    return (u & 0x80000000u) ? __uint_as_float(u ^ 0x80000000u) : __uint_as_float(~u);
}
__device__ __forceinline__ uint32_t smem_u32(const void* p) {
    uint32_t a;
    asm("{ .reg .u64 t; cvta.to.shared.u64 t, %1; cvt.u32.u64 %0, t; }" : "=r"(a) : "l"(p));
    return a;
}
__device__ __forceinline__ void cp_async16(uint32_t dst, const void* src) {
    asm volatile("cp.async.cg.shared.global [%0], [%1], 16;" :: "r"(dst), "l"(src) : "memory");
}
__device__ __forceinline__ void cp_commit() {
    asm volatile("cp.async.commit_group;" ::: "memory");
}
template <int N>
__device__ __forceinline__ void cp_wait() {
    asm volatile("cp.async.wait_group %0;" :: "n"(N) : "memory");
}
__device__ __forceinline__ void ldm_x4(uint32_t r[4], uint32_t addr) {
    asm volatile("ldmatrix.sync.aligned.m8n8.x4.shared.b16 {%0,%1,%2,%3}, [%4];"
                 : "=r"(r[0]), "=r"(r[1]), "=r"(r[2]), "=r"(r[3]) : "r"(addr));
}
__device__ __forceinline__ void mma16816(float d[4], const uint32_t a[4],
                                         uint32_t b0, uint32_t b1) {
    asm volatile(
        "mma.sync.aligned.m16n8k16.row.col.f32.f16.f16.f32 "
        "{%0,%1,%2,%3},{%4,%5,%6,%7},{%8,%9},{%0,%1,%2,%3};"
        : "+f"(d[0]), "+f"(d[1]), "+f"(d[2]), "+f"(d[3])
        : "r"(a[0]), "r"(a[1]), "r"(a[2]), "r"(a[3]), "r"(b0), "r"(b1));
}
__device__ __forceinline__ uint32_t swz(uint32_t off) {
    return off ^ ((off >> 3) & 0x70);
}

// ---------------- prep: fp16 pack + norms + njl + inits; 2 rows/warp ----------------
__global__ void prep_kernel(const float* __restrict__ E, const void* __restrict__ lab) {
    int warp = threadIdx.x >> 5, lane = threadIdx.x & 31;
    int r0 = blockIdx.x * 16 + warp * 2;
    if (threadIdx.x < 16) {
        int idx = blockIdx.x * 16 + threadIdx.x;
        g_v[idx] = make_uint2(0u, 0xFFFFFFFFu);
    }
    if (blockIdx.x == 0 && threadIdx.x == 0) g_cnt = 0u;

    // 4 independent 16B loads up front (MLP)
    const float4* e0 = (const float4*)(E + (size_t)r0 * Ddim);
    const float4* e1 = (const float4*)(E + (size_t)(r0 + 1) * Ddim);
    float4 v[4];
    v[0] = e0[lane * 2]; v[1] = e0[lane * 2 + 1];
    v[2] = e1[lane * 2]; v[3] = e1[lane * 2 + 1];

    float s[2] = {0.f, 0.f};
    #pragma unroll
    for (int rr = 0; rr < 2; rr++) {
        float x[8];
        x[0] = v[rr * 2].x; x[1] = v[rr * 2].y; x[2] = v[rr * 2].z; x[3] = v[rr * 2].w;
        x[4] = v[rr * 2 + 1].x; x[5] = v[rr * 2 + 1].y; x[6] = v[rr * 2 + 1].z; x[7] = v[rr * 2 + 1].w;
        __half h[8];
        #pragma unroll
        for (int i = 0; i < 8; i++) {
            s[rr] += x[i] * x[i];
            h[i] = __float2half(x[i]);
        }
        *(uint4*)(g_h + (size_t)(r0 + rr) * Ddim + lane * 8) = *(const uint4*)h;
    }
    #pragma unroll
    for (int o = 16; o; o >>= 1) {
        s[0] += __shfl_xor_sync(0xFFFFFFFFu, s[0], o);
        s[1] += __shfl_xor_sync(0xFFFFFFFFu, s[1], o);
    }
    if (lane == 0) {
        const int* li = (const int*)lab;
        int all0 = 1;
        #pragma unroll
        for (int i = 0; i < 32; i++)
            if (li[2 * i + 1] != 0) all0 = 0;
        #pragma unroll
        for (int rr = 0; rr < 2; rr++) {
            int row = r0 + rr;
            int lb = all0 ? (int)((const long long*)lab)[row] : li[row];
            g_norms[row] = s[rr];
            g_njl[row] = make_float2(s[rr], __int_as_float(lb));
        }
    }
}

// ---------------- main fused kernel ----------------
// CTA tile 128 x 256; 8 warps, each 64x64; single-pass fp16 MMA.
// All 4 k-chunks quad-buffered upfront; one __syncthreads per chunk.
// Last CTA (atomic counter) computes the final scalar loss.
__global__ __launch_bounds__(256, 1) void mine_kernel(float* __restrict__ out) {
    extern __shared__ char smem[];
    const uint32_t sb = smem_u32(smem);
    const int tid  = threadIdx.x;
    const int wid  = tid >> 5;
    const int lane = tid & 31;
    const int wr   = wid & 1;          // 64-row group
    const int wc   = wid >> 1;         // 64-col group (0..3)

    // map blockIdx -> (jt, it) with it <= 2*jt+1
    int jt = 0, rem = blockIdx.x;
    while (rem >= 2 * jt + 2) { rem -= 2 * jt + 2; jt++; }
    const int it   = rem;
    const int row0 = it * 128;
    const int col0 = jt * 256;

    if (tid < 128) ((float2*)(smem + SM_NJR))[tid] = g_njl[row0 + tid];
    ((float2*)(smem + SM_NJC))[tid] = g_njl[col0 + tid];

    // one 64-wide k-chunk: A(128r x 8seg) + B(256r x 8seg) = 3072 16B segs; 12/thread
    auto issue_chunk = [&](int kc, int b) {
        #pragma unroll
        for (int i = 0; i < 12; i++) {
            int u = i * 256 + tid;
            int s, grow;
            uint32_t arroff;
            if (u < 1024) { s = u;        grow = row0 + (s >> 3); arroff = SM_A; }
            else          { s = u - 1024; grow = col0 + (s >> 3); arroff = SM_B; }
            int r = s >> 3, q = s & 7;
            const void* src = g_h + (size_t)grow * Ddim + kc * 64 + q * 8;
            uint32_t dst = sb + SM_BUF(b) + arroff + swz((uint32_t)(r * 128 + q * 16));
            cp_async16(dst, src);
        }
        cp_commit();
    };

    float acc[4][8][4];
    #pragma unroll
    for (int ar = 0; ar < 4; ar++)
        #pragma unroll
        for (int na = 0; na < 8; na++)
            #pragma unroll
            for (int e = 0; e < 4; e++) acc[ar][na][e] = 0.f;

    const int Rb = wr * 64;
    const int Cb = wc * 64;
    const int seg = lane >> 3;
    const int l7  = lane & 7;
    const int a_radd = (seg & 1) * 8 + l7;
    const int a_koff = (seg >> 1) * 16;
    const int b_radd = (seg >> 1) * 8 + l7;
    const int b_koff = (seg & 1) * 16;

    issue_chunk(0, 0);
    issue_chunk(1, 1);
    issue_chunk(2, 2);
    issue_chunk(3, 3);

    #pragma unroll
    for (int kc = 0; kc < 4; kc++) {
        if      (kc == 0) cp_wait<3>();
        else if (kc == 1) cp_wait<2>();
        else if (kc == 2) cp_wait<1>();
        else              cp_wait<0>();
        __syncthreads();

        #pragma unroll
        for (int ks = 0; ks < 4; ks++) {
            uint32_t ah[4][4], bh[4][4];
            #pragma unroll
            for (int ar = 0; ar < 4; ar++) {
                uint32_t off = swz((uint32_t)((Rb + ar * 16 + a_radd) * 128 + ks * 32 + a_koff));
                ldm_x4(ah[ar], sb + SM_BUF(kc) + SM_A + off);
            }
            #pragma unroll
            for (int i = 0; i < 4; i++) {
                uint32_t off = swz((uint32_t)((Cb + i * 16 + b_radd) * 128 + ks * 32 + b_koff));
                ldm_x4(bh[i], sb + SM_BUF(kc) + SM_B + off);
            }
            #pragma unroll
            for (int ar = 0; ar < 4; ar++)
                #pragma unroll
                for (int na = 0; na < 8; na++) {
                    const int i = na >> 1, sel = (na & 1) * 2;
                    mma16816(acc[ar][na], ah[ar], bh[i][sel], bh[i][sel + 1]);
                }
        }
    }

    // ---- epilogue: dual-direction batch-hard fold ----
    const int g  = lane >> 2;
    const int qp = lane & 3;

    int   rowG[8];  float nR[8];  int lR[8];
    int   colG[16]; float nC[16]; int lC[16];
    const float2* njr = (const float2*)(smem + SM_NJR);
    const float2* njc = (const float2*)(smem + SM_NJC);
    #pragma unroll
    for (int ar = 0; ar < 4; ar++)
        #pragma unroll
        for (int h = 0; h < 2; h++) {
            int lr = Rb + ar * 16 + g + h * 8;
            int k = ar * 2 + h;
            rowG[k] = row0 + lr;
            nR[k] = njr[lr].x; lR[k] = __float_as_int(njr[lr].y);
        }
    #pragma unroll
    for (int na = 0; na < 8; na++)
        #pragma unroll
        for (int p = 0; p < 2; p++) {
            int lc = Cb + na * 8 + qp * 2 + p;
            int k = na * 2 + p;
            colG[k] = col0 + lc;
            nC[k] = njc[lc].x; lC[k] = __float_as_int(njc[lc].y);
        }

    float rp[8], rn[8], cpx[16], cn[16];
    #pragma unroll
    for (int k = 0; k < 8; k++)  { rp[k] = -1e30f; rn[k] = 1e30f; }
    #pragma unroll
    for (int k = 0; k < 16; k++) { cpx[k] = -1e30f; cn[k] = 1e30f; }

    #pragma unroll
    for (int ar = 0; ar < 4; ar++)
        #pragma unroll
        for (int na = 0; na < 8; na++)
            #pragma unroll
            for (int e = 0; e < 4; e++) {
                const int ri = ar * 2 + (e >> 1);
                const int ci = na * 2 + (e & 1);
                const float w  = -2.f * acc[ar][na][e];
                const float vr = w + nC[ci];
                const float vc = w + nR[ri];
                if (lR[ri] == lC[ci]) {
                    if (rowG[ri] != colG[ci]) {
                        rp[ri]  = fmaxf(rp[ri], vr);
                        cpx[ci] = fmaxf(cpx[ci], vc);
                    }
                } else {
                    rn[ri] = fminf(rn[ri], vr);
                    cn[ci] = fminf(cn[ci], vc);
                }
            }

    #pragma unroll
    for (int o = 1; o <= 2; o <<= 1)
        #pragma unroll
        for (int k = 0; k < 8; k++) {
            rp[k] = fmaxf(rp[k], __shfl_xor_sync(0xFFFFFFFFu, rp[k], o));
            rn[k] = fminf(rn[k], __shfl_xor_sync(0xFFFFFFFFu, rn[k], o));
        }
    #pragma unroll
    for (int o = 4; o <= 16; o <<= 1)
        #pragma unroll
        for (int k = 0; k < 16; k++) {
            cpx[k] = fmaxf(cpx[k], __shfl_xor_sync(0xFFFFFFFFu, cpx[k], o));
            cn[k]  = fminf(cn[k],  __shfl_xor_sync(0xFFFFFFFFu, cn[k], o));
        }

    if (qp == 0) {
        #pragma unroll
        for (int k = 0; k < 8; k++) {
            if (rp[k] > -1e29f) atomicMax(&g_v[rowG[k]].x, enc(rp[k]));
            if (rn[k] <  1e29f) atomicMin(&g_v[rowG[k]].y, enc(rn[k]));
        }
    }
    if (g == 0) {
        #pragma unroll
        for (int k = 0; k < 16; k++) {
            if (cpx[k] > -1e29f) atomicMax(&g_v[colG[k]].x, enc(cpx[k]));
            if (cn[k]  <  1e29f) atomicMin(&g_v[colG[k]].y, enc(cn[k]));
        }
    }

    // ---- fused finalize: last CTA reduces g_v to the scalar loss ----
    __threadfence();
    __syncthreads();
    __shared__ unsigned int s_rank;
    if (tid == 0) s_rank = atomicAdd(&g_cnt, 1u);
    __syncthreads();
    if (s_rank == NGRID - 1) {
        float s = 0.f, vcnt = 0.f;
        #pragma unroll
        for (int k = 0; k < 32; k++) {
            int i = tid + k * 256;
            uint2 u = __ldcg(&g_v[i]);
            float ni = __ldcg(&g_norms[i]);
            float vp = dec(u.x);
            float vn = dec(u.y);
            if (vp > -1e29f && vn < 1e29f) {
                float dp = sqrtf(fmaxf(vp + ni, 0.f));
                float dn = sqrtf(fmaxf(vn + ni, 0.f));
                s += fmaxf(dp - dn + MARGIN, 0.f);
                vcnt += 1.f;
            }
        }
        #pragma unroll
        for (int o = 16; o; o >>= 1) {
            s    += __shfl_xor_sync(0xFFFFFFFFu, s, o);
            vcnt += __shfl_xor_sync(0xFFFFFFFFu, vcnt, o);
        }
        float* red = (float*)(smem + SM_NJR);   // reuse smem
        if (lane == 0) { red[wid] = s; red[wid + 8] = vcnt; }
        __syncthreads();
        if (tid == 0) {
            float ts = 0.f, tv = 0.f;
            #pragma unroll
            for (int w = 0; w < 8; w++) { ts += red[w]; tv += red[w + 8]; }
            out[0] = (tv > 0.f) ? (ts / fmaxf(tv, 1.f)) : 0.f;
        }
    }
}

extern "C" void kernel_launch(void* const* d_in, const int* in_sizes, int n_in,
                              void* d_out, int out_size) {
    const float* E   = (const float*)d_in[0];
    const void*  lab = d_in[1];

    cudaFuncSetAttribute(mine_kernel, cudaFuncAttributeMaxDynamicSharedMemorySize, SMEM_TOTAL);

    prep_kernel<<<Bsz / 16, 256>>>(E, lab);
    mine_kernel<<<NGRID, 256, SMEM_TOTAL>>>((float*)d_out);
}

// round 17
// speedup vs baseline: 1.7168x; 1.7168x over previous
#include <cuda_runtime.h>
#include <cuda_fp16.h>
#include <math.h>
#include <stdint.h>

#define Bsz    8192
#define Ddim   256
#define MARGIN 0.3f
#define NT     64
#define NTILES (NT * (NT + 1) / 2)   // 2080

// ---- dynamic SMEM per CTA: 2 bufs x (A 16KB + B 16KB) + njr(1KB) + njc(1KB) ----
#define SM_BUF(b)   ((b) * 32768)
#define SM_A        0
#define SM_B        16384
#define SM_NJR      65536
#define SM_NJC      66560
#define SMEM_TOTAL  67584

__device__ float  g_norms[Bsz];
__device__ float2 g_njl[Bsz];
__device__ __half g_h[Bsz * Ddim];
__device__ uint2  g_v[Bsz];       // {enc(max pos v), enc(min neg v)}

__device__ __forceinline__ unsigned int enc(float f) {
    unsigned int u = __float_as_uint(f);
    return (u & 0x80000000u) ? ~u : (u | 0x80000000u);
}
__device__ __forceinline__ float dec(unsigned int u) {
    return (u & 0x80000000u) ? __uint_as_float(u ^ 0x80000000u) : __uint_as_float(~u);
}
__device__ __forceinline__ uint32_t smem_u32(const void* p) {
    uint32_t a;
    asm("{ .reg .u64 t; cvta.to.shared.u64 t, %1; cvt.u32.u64 %0, t; }" : "=r"(a) : "l"(p));
    return a;
}
__device__ __forceinline__ void cp_async16(uint32_t dst, const void* src) {
    asm volatile("cp.async.cg.shared.global [%0], [%1], 16;" :: "r"(dst), "l"(src) : "memory");
}
__device__ __forceinline__ void cp_commit() {
    asm volatile("cp.async.commit_group;" ::: "memory");
}
template <int N>
__device__ __forceinline__ void cp_wait() {
    asm volatile("cp.async.wait_group %0;" :: "n"(N) : "memory");
}
__device__ __forceinline__ void ldm_x4(uint32_t r[4], uint32_t addr) {
    asm volatile("ldmatrix.sync.aligned.m8n8.x4.shared.b16 {%0,%1,%2,%3}, [%4];"
                 : "=r"(r[0]), "=r"(r[1]), "=r"(r[2]), "=r"(r[3]) : "r"(addr));
}
__device__ __forceinline__ void mma16816(float d[4], const uint32_t a[4],
                                         uint32_t b0, uint32_t b1) {
    asm volatile(
        "mma.sync.aligned.m16n8k16.row.col.f32.f16.f16.f32 "
        "{%0,%1,%2,%3},{%4,%5,%6,%7},{%8,%9},{%0,%1,%2,%3};"
        : "+f"(d[0]), "+f"(d[1]), "+f"(d[2]), "+f"(d[3])
        : "r"(a[0]), "r"(a[1]), "r"(a[2]), "r"(a[3]), "r"(b0), "r"(b1));
}
__device__ __forceinline__ uint32_t swz(uint32_t off) {
    return off ^ ((off >> 3) & 0x70);
}

// ---------------- prep: fp16 pack + norms + njl + inits; 2 rows/warp ----------------
__global__ void prep_kernel(const float* __restrict__ E, const void* __restrict__ lab) {
    int warp = threadIdx.x >> 5, lane = threadIdx.x & 31;
    int r0 = blockIdx.x * 16 + warp * 2;
    if (threadIdx.x < 16) {
        int idx = blockIdx.x * 16 + threadIdx.x;
        g_v[idx] = make_uint2(0u, 0xFFFFFFFFu);
    }
    const float4* e0 = (const float4*)(E + (size_t)r0 * Ddim);
    const float4* e1 = (const float4*)(E + (size_t)(r0 + 1) * Ddim);
    float4 v[4];
    v[0] = e0[lane * 2]; v[1] = e0[lane * 2 + 1];
    v[2] = e1[lane * 2]; v[3] = e1[lane * 2 + 1];

    float s[2] = {0.f, 0.f};
    #pragma unroll
    for (int rr = 0; rr < 2; rr++) {
        float x[8];
        x[0] = v[rr * 2].x; x[1] = v[rr * 2].y; x[2] = v[rr * 2].z; x[3] = v[rr * 2].w;
        x[4] = v[rr * 2 + 1].x; x[5] = v[rr * 2 + 1].y; x[6] = v[rr * 2 + 1].z; x[7] = v[rr * 2 + 1].w;
        __half h[8];
        #pragma unroll
        for (int i = 0; i < 8; i++) {
            s[rr] += x[i] * x[i];
            h[i] = __float2half(x[i]);
        }
        *(uint4*)(g_h + (size_t)(r0 + rr) * Ddim + lane * 8) = *(const uint4*)h;
    }
    #pragma unroll
    for (int o = 16; o; o >>= 1) {
        s[0] += __shfl_xor_sync(0xFFFFFFFFu, s[0], o);
        s[1] += __shfl_xor_sync(0xFFFFFFFFu, s[1], o);
    }
    if (lane == 0) {
        const int* li = (const int*)lab;
        int all0 = 1;
        #pragma unroll
        for (int i = 0; i < 32; i++)
            if (li[2 * i + 1] != 0) all0 = 0;
        #pragma unroll
        for (int rr = 0; rr < 2; rr++) {
            int row = r0 + rr;
            int lb = all0 ? (int)((const long long*)lab)[row] : li[row];
            g_norms[row] = s[rr];
            g_njl[row] = make_float2(s[rr], __int_as_float(lb));
        }
    }
}

// ---------------- main fused kernel ----------------
// CTA tile 128 x 128; 4 warps (2x2), each 64x64; single-pass fp16 MMA.
// 128 threads/CTA -> 2 CTAs resident per SM (reg- and smem-feasible).
__global__ __launch_bounds__(128, 2) void mine_kernel() {
    extern __shared__ char smem[];
    const uint32_t sb = smem_u32(smem);
    const int tid  = threadIdx.x;
    const int wid  = tid >> 5;
    const int lane = tid & 31;
    const int wr   = wid & 1;          // 64-row group
    const int wc   = wid >> 1;         // 64-col group

    // map blockIdx -> (it, jt), it <= jt
    int it = 0, rem = blockIdx.x;
    while (rem >= NT - it) { rem -= NT - it; it++; }
    const int jt   = it + rem;
    const int row0 = it * 128;
    const int col0 = jt * 128;

    if (tid < 128) {
        ((float2*)(smem + SM_NJR))[tid] = g_njl[row0 + tid];
        ((float2*)(smem + SM_NJC))[tid] = g_njl[col0 + tid];
    }

    // one 64-wide k-chunk: A(128r x 8seg) + B(128r x 8seg) = 2048 segs; 16/thread
    auto issue_chunk = [&](int kc, int b) {
        #pragma unroll
        for (int i = 0; i < 16; i++) {
            int u = i * 128 + tid;
            int s, grow;
            uint32_t arroff;
            if (u < 1024) { s = u;        grow = row0 + (s >> 3); arroff = SM_A; }
            else          { s = u - 1024; grow = col0 + (s >> 3); arroff = SM_B; }
            int r = s >> 3, q = s & 7;
            const void* src = g_h + (size_t)grow * Ddim + kc * 64 + q * 8;
            uint32_t dst = sb + SM_BUF(b) + arroff + swz((uint32_t)(r * 128 + q * 16));
            cp_async16(dst, src);
        }
        cp_commit();
    };

    float acc[4][8][4];
    #pragma unroll
    for (int ar = 0; ar < 4; ar++)
        #pragma unroll
        for (int na = 0; na < 8; na++)
            #pragma unroll
            for (int e = 0; e < 4; e++) acc[ar][na][e] = 0.f;

    const int Rb = wr * 64;
    const int Cb = wc * 64;
    const int seg = lane >> 3;
    const int l7  = lane & 7;
    const int a_radd = (seg & 1) * 8 + l7;
    const int a_koff = (seg >> 1) * 16;
    const int b_radd = (seg >> 1) * 8 + l7;
    const int b_koff = (seg & 1) * 16;

    issue_chunk(0, 0);
    #pragma unroll
    for (int kc = 0; kc < 4; kc++) {
        const int b = kc & 1;
        if (kc < 3) { issue_chunk(kc + 1, b ^ 1); cp_wait<1>(); }
        else        { cp_wait<0>(); }
        __syncthreads();

        #pragma unroll
        for (int ks = 0; ks < 4; ks++) {
            uint32_t ah[4][4], bh[4][4];
            #pragma unroll
            for (int ar = 0; ar < 4; ar++) {
                uint32_t off = swz((uint32_t)((Rb + ar * 16 + a_radd) * 128 + ks * 32 + a_koff));
                ldm_x4(ah[ar], sb + SM_BUF(b) + SM_A + off);
            }
            #pragma unroll
            for (int i = 0; i < 4; i++) {
                uint32_t off = swz((uint32_t)((Cb + i * 16 + b_radd) * 128 + ks * 32 + b_koff));
                ldm_x4(bh[i], sb + SM_BUF(b) + SM_B + off);
            }
            #pragma unroll
            for (int ar = 0; ar < 4; ar++)
                #pragma unroll
                for (int na = 0; na < 8; na++) {
                    const int i = na >> 1, sel = (na & 1) * 2;
                    mma16816(acc[ar][na], ah[ar], bh[i][sel], bh[i][sel + 1]);
                }
        }
        __syncthreads();
    }

    // ---- epilogue: dual-direction batch-hard fold ----
    const int g  = lane >> 2;
    const int qp = lane & 3;

    int   rowG[8];  float nR[8];  int lR[8];
    int   colG[16]; float nC[16]; int lC[16];
    const float2* njr = (const float2*)(smem + SM_NJR);
    const float2* njc = (const float2*)(smem + SM_NJC);
    #pragma unroll
    for (int ar = 0; ar < 4; ar++)
        #pragma unroll
        for (int h = 0; h < 2; h++) {
            int lr = Rb + ar * 16 + g + h * 8;
            int k = ar * 2 + h;
            rowG[k] = row0 + lr;
            nR[k] = njr[lr].x; lR[k] = __float_as_int(njr[lr].y);
        }
    #pragma unroll
    for (int na = 0; na < 8; na++)
        #pragma unroll
        for (int p = 0; p < 2; p++) {
            int lc = Cb + na * 8 + qp * 2 + p;
            int k = na * 2 + p;
            colG[k] = col0 + lc;
            nC[k] = njc[lc].x; lC[k] = __float_as_int(njc[lc].y);
        }

    float rp[8], rn[8], cpx[16], cn[16];
    #pragma unroll
    for (int k = 0; k < 8; k++)  { rp[k] = -1e30f; rn[k] = 1e30f; }
    #pragma unroll
    for (int k = 0; k < 16; k++) { cpx[k] = -1e30f; cn[k] = 1e30f; }

    #pragma unroll
    for (int ar = 0; ar < 4; ar++)
        #pragma unroll
        for (int na = 0; na < 8; na++)
            #pragma unroll
            for (int e = 0; e < 4; e++) {
                const int ri = ar * 2 + (e >> 1);
                const int ci = na * 2 + (e & 1);
                const float w  = -2.f * acc[ar][na][e];
                const float vr = w + nC[ci];
                const float vc = w + nR[ri];
                if (lR[ri] == lC[ci]) {
                    if (rowG[ri] != colG[ci]) {
                        rp[ri]  = fmaxf(rp[ri], vr);
                        cpx[ci] = fmaxf(cpx[ci], vc);
                    }
                } else {
                    rn[ri] = fminf(rn[ri], vr);
                    cn[ci] = fminf(cn[ci], vc);
                }
            }

    #pragma unroll
    for (int o = 1; o <= 2; o <<= 1)
        #pragma unroll
        for (int k = 0; k < 8; k++) {
            rp[k] = fmaxf(rp[k], __shfl_xor_sync(0xFFFFFFFFu, rp[k], o));
            rn[k] = fminf(rn[k], __shfl_xor_sync(0xFFFFFFFFu, rn[k], o));
        }
    #pragma unroll
    for (int o = 4; o <= 16; o <<= 1)
        #pragma unroll
        for (int k = 0; k < 16; k++) {
            cpx[k] = fmaxf(cpx[k], __shfl_xor_sync(0xFFFFFFFFu, cpx[k], o));
            cn[k]  = fminf(cn[k],  __shfl_xor_sync(0xFFFFFFFFu, cn[k], o));
        }

    if (qp == 0) {
        #pragma unroll
        for (int k = 0; k < 8; k++) {
            if (rp[k] > -1e29f) atomicMax(&g_v[rowG[k]].x, enc(rp[k]));
            if (rn[k] <  1e29f) atomicMin(&g_v[rowG[k]].y, enc(rn[k]));
        }
    }
    if (g == 0) {
        #pragma unroll
        for (int k = 0; k < 16; k++) {
            if (cpx[k] > -1e29f) atomicMax(&g_v[colG[k]].x, enc(cpx[k]));
            if (cn[k]  <  1e29f) atomicMin(&g_v[colG[k]].y, enc(cn[k]));
        }
    }
}

// ---------------- finalize ----------------
__global__ void finalize_kernel(float* out) {
    __shared__ float ss[32], sv[32];
    int tid = threadIdx.x;
    uint2 u[8]; float ni[8];
    #pragma unroll
    for (int k = 0; k < 8; k++) {
        u[k]  = g_v[tid + k * 1024];
        ni[k] = g_norms[tid + k * 1024];
    }
    float s = 0.f, v = 0.f;
    #pragma unroll
    for (int k = 0; k < 8; k++) {
        float vp = dec(u[k].x);
        float vn = dec(u[k].y);
        if (vp > -1e29f && vn < 1e29f) {
            float dp = sqrtf(fmaxf(vp + ni[k], 0.f));
            float dn = sqrtf(fmaxf(vn + ni[k], 0.f));
            s += fmaxf(dp - dn + MARGIN, 0.f);
            v += 1.f;
        }
    }
    #pragma unroll
    for (int o = 16; o; o >>= 1) {
        s += __shfl_xor_sync(0xFFFFFFFFu, s, o);
        v += __shfl_xor_sync(0xFFFFFFFFu, v, o);
    }
    int warp = tid >> 5, lane = tid & 31;
    if (lane == 0) { ss[warp] = s; sv[warp] = v; }
    __syncthreads();
    if (warp == 0) {
        s = ss[lane]; v = sv[lane];
        #pragma unroll
        for (int o = 16; o; o >>= 1) {
            s += __shfl_xor_sync(0xFFFFFFFFu, s, o);
            v += __shfl_xor_sync(0xFFFFFFFFu, v, o);
        }
        if (lane == 0) out[0] = (v > 0.f) ? (s / fmaxf(v, 1.f)) : 0.f;
    }
}

extern "C" void kernel_launch(void* const* d_in, const int* in_sizes, int n_in,
                              void* d_out, int out_size) {
    const float* E   = (const float*)d_in[0];
    const void*  lab = d_in[1];

    cudaFuncSetAttribute(mine_kernel, cudaFuncAttributeMaxDynamicSharedMemorySize, SMEM_TOTAL);

    prep_kernel<<<Bsz / 16, 256>>>(E, lab);
    mine_kernel<<<NTILES, 128, SMEM_TOTAL>>>();
    finalize_kernel<<<1, 1024>>>((float*)d_out);
}